// round 16
// baseline (speedup 1.0000x reference)
#include <cuda_runtime.h>
#include <cuda_bf16.h>
#include <cstdint>
#include <cstddef>

// ---------------- problem constants ----------------
#define NTOT   100000
#define NPT    50000
#define NPG    50000
#define EG     500000
#define NG     4
#define NH     4
#define HD     64
#define HID    64
#define DD     256
#define OUTD   64
#define TT     20000

typedef unsigned long long u64;

// ---------------- device scratch (static, no allocs) ----------------
__device__ float g_transformed[(size_t)NTOT * HID];
__device__ __nv_bfloat16 g_semWbt[2 * 256 * 256];      // sem_W bf16 transposed [b][n][k]
__device__ uint32_t g_gatWhi[4 * 256 * 32];            // gat_W bf16 hi [g][n][kpair]
__device__ uint32_t g_gatWlo[4 * 256 * 32];            // gat_W bf16 lo residual
__device__ uint32_t g_fcWhi[2 * 64 * 128];             // fc_W bf16 hi [ty][n][kpair]
__device__ uint32_t g_fcWlo[2 * 64 * 128];             // fc_W bf16 lo residual
__device__ float g_z[(size_t)NG * NPG * DD];
__device__ float g_el[NG * NPG * NH];
__device__ float g_er[NG * NPG * NH];
__device__ int   g_cnt[NG * NPG];
__device__ int   g_cur[NG * NPG];
__device__ int   g_offs[NG * (NPG + 1)];
__device__ int   g_csr[NG * EG];
__device__ int   g_flag[NG * NPG];
__device__ int   g_list[NG * TT];
__device__ int   g_wcnt[NG];
__device__ float g_o[(size_t)NG * NPG * DD];
__device__ float g_wsum[NG];
__device__ float g_beta[NG];

__device__ __forceinline__ float lrelu(float x) { return fmaxf(x, 0.2f * x); }
__device__ __forceinline__ float tanh_fast(float x) {
    float y; asm("tanh.approx.f32 %0, %1;" : "=f"(y) : "f"(x)); return y;
}
__device__ __forceinline__ void fma2(u64& acc, u64 a, u64 b) {
    asm("fma.rn.f32x2 %0, %1, %2, %0;" : "+l"(acc) : "l"(a), "l"(b));
}
__device__ __forceinline__ float2 unpack2(u64 v) {
    float2 r; asm("mov.b64 {%0, %1}, %2;" : "=f"(r.x), "=f"(r.y) : "l"(v)); return r;
}
// pack (lo,hi) floats into bf16x2 (lo = element 0)
__device__ __forceinline__ uint32_t bf2(float lo, float hi) {
    uint32_t r; asm("cvt.rn.bf16x2.f32 %0, %1, %2;" : "=r"(r) : "f"(hi), "f"(lo)); return r;
}
__device__ __forceinline__ void mma_bf16(float& c0, float& c1, float& c2, float& c3,
                                         uint32_t a0, uint32_t a1, uint32_t a2, uint32_t a3,
                                         uint32_t b0, uint32_t b1) {
    asm("mma.sync.aligned.m16n8k16.row.col.f32.bf16.bf16.f32 "
        "{%0,%1,%2,%3},{%4,%5,%6,%7},{%8,%9},{%0,%1,%2,%3};"
        : "+f"(c0), "+f"(c1), "+f"(c2), "+f"(c3)
        : "r"(a0), "r"(a1), "r"(a2), "r"(a3), "r"(b0), "r"(b1));
}

// ---------------- weight prep ----------------
__global__ void k_tw(const float* __restrict__ fcW, const float* __restrict__ semW,
                     const float* __restrict__ gatW) {
    int i = blockIdx.x * blockDim.x + threadIdx.x;
    if (i < 2 * 256 * 256) {                   // semWbt [b][n][k] <- semW [b][k][n]
        int b = i >> 16, rem = i & 65535, n = rem >> 8, k = rem & 255;
        g_semWbt[i] = __float2bfloat16(semW[b * 65536 + k * 256 + n]);
    }
    int j2 = i - 2 * 256 * 256;
    if (j2 >= 0 && j2 < 4 * 256 * 32) {        // gat hi/lo [g][n][kpair]
        int g = j2 >> 13, rem = j2 & 8191, n = rem >> 5, kp = rem & 31;
        const float* Wg = gatW + (size_t)g * 64 * 256;
        float w0 = Wg[(2 * kp) * 256 + n];
        float w1 = Wg[(2 * kp + 1) * 256 + n];
        uint32_t hp = bf2(w0, w1);
        g_gatWhi[j2] = hp;
        float h0 = __uint_as_float(hp << 16);
        float h1 = __uint_as_float(hp & 0xffff0000u);
        g_gatWlo[j2] = bf2(w0 - h0, w1 - h1);
    }
    int j3 = i - 2 * 256 * 256 - 4 * 256 * 32;
    if (j3 >= 0 && j3 < 2 * 64 * 128) {        // fc hi/lo [ty][n][kpair], fcW is [ty][o][k]
        int ty = j3 >> 13, rem = j3 & 8191, n = rem >> 7, kp = rem & 127;
        const float* Wt = fcW + ty * 16384 + n * 256;
        float w0 = Wt[2 * kp];
        float w1 = Wt[2 * kp + 1];
        uint32_t hp = bf2(w0, w1);
        g_fcWhi[j3] = hp;
        float h0 = __uint_as_float(hp << 16);
        float h1 = __uint_as_float(hp & 0xffff0000u);
        g_fcWlo[j3] = bf2(w0 - h0, w1 - h1);
    }
}

// ---------------- zero per-call scratch ----------------
__global__ void k_zero() {
    int i = blockIdx.x * blockDim.x + threadIdx.x;
    if (i < NG * NPG) { g_cnt[i] = 0; g_cur[i] = 0; g_flag[i] = 0; }
    if (i < NG) { g_wsum[i] = 0.f; g_wcnt[i] = 0; }
}

// ---------------- 1: type FC via split-bf16 MMA, staged coalesced store ----------------
#define FC_S 132
#define FCT_S 68
__global__ void k_fc(const float* __restrict__ f0, const float* __restrict__ f1,
                     const float* __restrict__ fcb, const int* __restrict__ type_idx) {
    __shared__ uint32_t ahi[32 * FC_S], alo[32 * FC_S];
    __shared__ float fct[32 * FCT_S];
    int ty = blockIdx.y;
    int row0 = blockIdx.x * 32;
    int t = threadIdx.x;
    const float* f = (ty == 0 ? f0 : f1);
    for (int i = t; i < 32 * 128; i += 256) {
        int r = i >> 7, c = i & 127;
        int rr = row0 + r; rr = rr < NPT ? rr : NPT - 1;
        float2 xv = *(const float2*)(f + (size_t)rr * 256 + c * 2);
        uint32_t hp = bf2(xv.x, xv.y);
        float h0 = __uint_as_float(hp << 16);
        float h1 = __uint_as_float(hp & 0xffff0000u);
        ahi[r * FC_S + c] = hp;
        alo[r * FC_S + c] = bf2(xv.x - h0, xv.y - h1);
    }
    __syncthreads();
    int wid = t >> 5, lane = t & 31;
    int gid = lane >> 2, tid = lane & 3;
    int mt = wid >> 2, cq = wid & 3;
    const uint32_t* Whi = g_fcWhi + ty * 8192;   // [n=64][kp=128]
    const uint32_t* Wlo = g_fcWlo + ty * 8192;
    float c[2][4] = {};                          // [ntile][reg]
    #pragma unroll
    for (int ks = 0; ks < 16; ks++) {
        int ab = ks * 8 + tid;
        int r = mt * 16 + gid;
        uint32_t a0 = ahi[r * FC_S + ab];
        uint32_t a1 = ahi[(r + 8) * FC_S + ab];
        uint32_t a2 = ahi[r * FC_S + ab + 4];
        uint32_t a3 = ahi[(r + 8) * FC_S + ab + 4];
        uint32_t v0 = alo[r * FC_S + ab];
        uint32_t v1 = alo[(r + 8) * FC_S + ab];
        uint32_t v2 = alo[r * FC_S + ab + 4];
        uint32_t v3 = alo[(r + 8) * FC_S + ab + 4];
        #pragma unroll
        for (int nt = 0; nt < 2; nt++) {
            int n = cq * 16 + nt * 8 + gid;
            uint32_t bh0 = Whi[n * 128 + ks * 8 + tid];
            uint32_t bh1 = Whi[n * 128 + ks * 8 + tid + 4];
            uint32_t bl0 = Wlo[n * 128 + ks * 8 + tid];
            uint32_t bl1 = Wlo[n * 128 + ks * 8 + tid + 4];
            mma_bf16(c[nt][0], c[nt][1], c[nt][2], c[nt][3], a0, a1, a2, a3, bh0, bh1);
            mma_bf16(c[nt][0], c[nt][1], c[nt][2], c[nt][3], a0, a1, a2, a3, bl0, bl1);
            mma_bf16(c[nt][0], c[nt][1], c[nt][2], c[nt][3], v0, v1, v2, v3, bh0, bh1);
        }
    }
    // stage into smem (bias added), then coalesced scatter via type_idx
    #pragma unroll
    for (int nt = 0; nt < 2; nt++) {
        int col = cq * 16 + nt * 8 + tid * 2;
        float2 bbv = *(const float2*)(fcb + ty * 64 + col);
        int r = mt * 16 + gid;
        fct[r * FCT_S + col]           = c[nt][0] + bbv.x;
        fct[r * FCT_S + col + 1]       = c[nt][1] + bbv.y;
        fct[(r + 8) * FCT_S + col]     = c[nt][2] + bbv.x;
        fct[(r + 8) * FCT_S + col + 1] = c[nt][3] + bbv.y;
    }
    __syncthreads();
    for (int i = t; i < 32 * 16; i += 256) {
        int r = i >> 4, c4 = i & 15;
        int rr = row0 + r;
        if (rr < NPT) {
            int d = type_idx[ty * NPT + rr];
            float4 v = *(const float4*)&fct[r * FCT_S + c4 * 4];
            *(float4*)(g_transformed + (size_t)d * 64 + c4 * 4) = v;
        }
    }
}

// ---------------- 2: gather + z = h @ gat_W via split-bf16 MMA, staged z store ----------------
#define GA_S 36
#define ZT_S 264
__global__ void k_gatz(const int* __restrict__ node_idx,
                       const float* __restrict__ al, const float* __restrict__ ar) {
    __shared__ uint32_t ahi[32 * GA_S], alo[32 * GA_S];
    __shared__ float sel[32][NH], ser[32][NH];
    __shared__ float zt[32 * ZT_S];
    int g = blockIdx.y;
    int row0 = blockIdx.x * 32;
    int t = threadIdx.x;
    if (t < 128) { sel[t >> 2][t & 3] = 0.f; ser[t >> 2][t & 3] = 0.f; }
    for (int i = t; i < 32 * 32; i += 256) {
        int r = i >> 5, c = i & 31;
        int rr = row0 + r; rr = rr < NPG ? rr : NPG - 1;
        int node = node_idx[g * NPG + rr];
        float2 xv = *(const float2*)(g_transformed + (size_t)node * 64 + c * 2);
        uint32_t hp = bf2(xv.x, xv.y);
        float h0 = __uint_as_float(hp << 16);
        float h1 = __uint_as_float(hp & 0xffff0000u);
        ahi[r * GA_S + c] = hp;
        alo[r * GA_S + c] = bf2(xv.x - h0, xv.y - h1);
    }
    __syncthreads();
    int wid = t >> 5, lane = t & 31;
    int gid = lane >> 2, tid = lane & 3;
    int n0 = wid * 32;
    const uint32_t* Whi = g_gatWhi + (size_t)g * 8192;
    const uint32_t* Wlo = g_gatWlo + (size_t)g * 8192;
    float c[2][4][4] = {};
    #pragma unroll
    for (int ks = 0; ks < 4; ks++) {
        int ab = ks * 8 + tid;
        uint32_t ah[2][4], av[2][4];
        #pragma unroll
        for (int mt = 0; mt < 2; mt++) {
            int r = mt * 16 + gid;
            ah[mt][0] = ahi[r * GA_S + ab];           av[mt][0] = alo[r * GA_S + ab];
            ah[mt][1] = ahi[(r + 8) * GA_S + ab];     av[mt][1] = alo[(r + 8) * GA_S + ab];
            ah[mt][2] = ahi[r * GA_S + ab + 4];       av[mt][2] = alo[r * GA_S + ab + 4];
            ah[mt][3] = ahi[(r + 8) * GA_S + ab + 4]; av[mt][3] = alo[(r + 8) * GA_S + ab + 4];
        }
        #pragma unroll
        for (int nt = 0; nt < 4; nt++) {
            int n = n0 + nt * 8 + gid;
            uint32_t bh0 = Whi[n * 32 + ks * 8 + tid];
            uint32_t bh1 = Whi[n * 32 + ks * 8 + tid + 4];
            uint32_t bl0 = Wlo[n * 32 + ks * 8 + tid];
            uint32_t bl1 = Wlo[n * 32 + ks * 8 + tid + 4];
            #pragma unroll
            for (int mt = 0; mt < 2; mt++) {
                mma_bf16(c[mt][nt][0], c[mt][nt][1], c[mt][nt][2], c[mt][nt][3],
                         ah[mt][0], ah[mt][1], ah[mt][2], ah[mt][3], bh0, bh1);
                mma_bf16(c[mt][nt][0], c[mt][nt][1], c[mt][nt][2], c[mt][nt][3],
                         ah[mt][0], ah[mt][1], ah[mt][2], ah[mt][3], bl0, bl1);
                mma_bf16(c[mt][nt][0], c[mt][nt][1], c[mt][nt][2], c[mt][nt][3],
                         av[mt][0], av[mt][1], av[mt][2], av[mt][3], bh0, bh1);
            }
        }
    }
    float pl[2][2] = {}, pr[2][2] = {};
    #pragma unroll
    for (int mt = 0; mt < 2; mt++) {
        #pragma unroll
        for (int nt = 0; nt < 4; nt++) {
            int col = n0 + nt * 8 + tid * 2;
            float2 av2 = *(const float2*)(al + g * DD + col);
            float2 rv2 = *(const float2*)(ar + g * DD + col);
            pl[mt][0] += c[mt][nt][0] * av2.x + c[mt][nt][1] * av2.y;
            pl[mt][1] += c[mt][nt][2] * av2.x + c[mt][nt][3] * av2.y;
            pr[mt][0] += c[mt][nt][0] * rv2.x + c[mt][nt][1] * rv2.y;
            pr[mt][1] += c[mt][nt][2] * rv2.x + c[mt][nt][3] * rv2.y;
            int r = mt * 16 + gid;
            zt[r * ZT_S + col]           = c[mt][nt][0];
            zt[r * ZT_S + col + 1]       = c[mt][nt][1];
            zt[(r + 8) * ZT_S + col]     = c[mt][nt][2];
            zt[(r + 8) * ZT_S + col + 1] = c[mt][nt][3];
        }
    }
    #pragma unroll
    for (int off = 1; off < 4; off <<= 1) {
        #pragma unroll
        for (int mt = 0; mt < 2; mt++) {
            #pragma unroll
            for (int rp = 0; rp < 2; rp++) {
                pl[mt][rp] += __shfl_xor_sync(~0u, pl[mt][rp], off);
                pr[mt][rp] += __shfl_xor_sync(~0u, pr[mt][rp], off);
            }
        }
    }
    if (tid == 0) {
        int h = wid >> 1;
        #pragma unroll
        for (int mt = 0; mt < 2; mt++) {
            #pragma unroll
            for (int rp = 0; rp < 2; rp++) {
                int r = mt * 16 + gid + rp * 8;
                atomicAdd(&sel[r][h], pl[mt][rp]);
                atomicAdd(&ser[r][h], pr[mt][rp]);
            }
        }
    }
    __syncthreads();
    if (t < 128) {
        int r = t >> 2, h = t & 3;
        int row = row0 + r;
        if (row < NPG) {
            g_el[((size_t)g * NPG + row) * NH + h] = sel[r][h];
            g_er[((size_t)g * NPG + row) * NH + h] = ser[r][h];
        }
    }
    // coalesced z store from staging tile
    for (int i = t; i < 32 * 64; i += 256) {
        int r = i >> 6, c4 = i & 63;
        int row = row0 + r;
        if (row < NPG) {
            float4 v = *(const float4*)&zt[r * ZT_S + c4 * 4];
            *(float4*)(g_z + ((size_t)g * NPG + row) * DD + c4 * 4) = v;
        }
    }
}

// ---------------- 3: CSR build ----------------
__global__ void k_count(const int* __restrict__ edst) {
    int i = blockIdx.x * blockDim.x + threadIdx.x;
    if (i < NG * EG) { int g = i / EG; atomicAdd(&g_cnt[g * NPG + edst[i]], 1); }
}

__global__ void k_scan() {
    int g = blockIdx.x;
    __shared__ int ssum[1024];
    int t = threadIdx.x;
    const int per = (NPG + 1023) / 1024;
    int beg = t * per, end = min(beg + per, NPG);
    int s = 0;
    for (int i = beg; i < end; i++) s += g_cnt[g * NPG + i];
    ssum[t] = s;
    __syncthreads();
    for (int off = 1; off < 1024; off <<= 1) {
        int v = (t >= off) ? ssum[t - off] : 0;
        __syncthreads();
        ssum[t] += v;
        __syncthreads();
    }
    int run = (t == 0) ? 0 : ssum[t - 1];
    for (int i = beg; i < end; i++) { g_offs[g * (NPG + 1) + i] = run; run += g_cnt[g * NPG + i]; }
    if (t == 1023) g_offs[g * (NPG + 1) + NPG] = run;
}

__global__ void k_scatter(const int* __restrict__ esrc, const int* __restrict__ edst) {
    int i = blockIdx.x * blockDim.x + threadIdx.x;
    if (i < NG * EG) {
        int g = i / EG;
        int d = edst[i];
        int pos = g_offs[g * (NPG + 1) + d] + atomicAdd(&g_cur[g * NPG + d], 1);
        g_csr[g * EG + pos] = esrc[i];
    }
}

__global__ void k_flag(const int* __restrict__ tgt) {
    int i = blockIdx.x * blockDim.x + threadIdx.x;
    if (i < NG * TT) {
        int g = i / TT;
        int d = tgt[i];
        if (atomicExch(&g_flag[g * NPG + d], 1) == 0) {
            int p = atomicAdd(&g_wcnt[g], 1);
            g_list[g * TT + p] = d;
        }
    }
}

// ---------------- 4: single-pass edge softmax + aggregation, 2x unrolled ----------------
__global__ void k_agg() {
    int g = blockIdx.y;
    int widx = blockIdx.x * 8 + (threadIdx.x >> 5);
    if (widx >= g_wcnt[g]) return;
    int lane = threadIdx.x & 31;
    int half = lane >> 4;
    int sub  = lane & 15;
    int h    = sub >> 2;
    int dst  = g_list[g * TT + widx];
    int beg = g_offs[g * (NPG + 1) + dst];
    int end = g_offs[g * (NPG + 1) + dst + 1];
    const int*   csr = g_csr + g * EG;
    const float* elg = g_el + (size_t)g * NPG * NH;
    const float* zg  = g_z + (size_t)g * NPG * DD;
    float erh = g_er[(g * NPG + dst) * NH + h];
    float acc[16] = {}, acc2[16] = {};
    float denom = 0.f;
    int i = beg + half;
    for (; i + 2 < end; i += 4) {          // 2 edges per half per iter (4 in flight/warp)
        int s0 = csr[i], s1 = csr[i + 2];
        float e0 = lrelu(elg[s0 * NH + h] + erh);
        float e1 = lrelu(elg[s1 * NH + h] + erh);
        float x0 = __expf(e0), x1 = __expf(e1);
        denom += x0 + x1;
        const float4* zp0 = (const float4*)(zg + (size_t)s0 * DD + sub * 16);
        const float4* zp1 = (const float4*)(zg + (size_t)s1 * DD + sub * 16);
        float4 a0 = zp0[0], b0 = zp0[1], c0 = zp0[2], d0 = zp0[3];
        float4 a1 = zp1[0], b1 = zp1[1], c1 = zp1[2], d1 = zp1[3];
        acc[0]  += x0 * a0.x; acc[1]  += x0 * a0.y; acc[2]  += x0 * a0.z; acc[3]  += x0 * a0.w;
        acc[4]  += x0 * b0.x; acc[5]  += x0 * b0.y; acc[6]  += x0 * b0.z; acc[7]  += x0 * b0.w;
        acc[8]  += x0 * c0.x; acc[9]  += x0 * c0.y; acc[10] += x0 * c0.z; acc[11] += x0 * c0.w;
        acc[12] += x0 * d0.x; acc[13] += x0 * d0.y; acc[14] += x0 * d0.z; acc[15] += x0 * d0.w;
        acc2[0]  += x1 * a1.x; acc2[1]  += x1 * a1.y; acc2[2]  += x1 * a1.z; acc2[3]  += x1 * a1.w;
        acc2[4]  += x1 * b1.x; acc2[5]  += x1 * b1.y; acc2[6]  += x1 * b1.z; acc2[7]  += x1 * b1.w;
        acc2[8]  += x1 * c1.x; acc2[9]  += x1 * c1.y; acc2[10] += x1 * c1.z; acc2[11] += x1 * c1.w;
        acc2[12] += x1 * d1.x; acc2[13] += x1 * d1.y; acc2[14] += x1 * d1.z; acc2[15] += x1 * d1.w;
    }
    for (; i < end; i += 2) {              // tail
        int src = csr[i];
        float e  = lrelu(elg[src * NH + h] + erh);
        float ex = __expf(e);
        denom += ex;
        const float4* zp = (const float4*)(zg + (size_t)src * DD + sub * 16);
        float4 a = zp[0], b = zp[1], c = zp[2], d = zp[3];
        acc[0]  += ex * a.x; acc[1]  += ex * a.y; acc[2]  += ex * a.z; acc[3]  += ex * a.w;
        acc[4]  += ex * b.x; acc[5]  += ex * b.y; acc[6]  += ex * b.z; acc[7]  += ex * b.w;
        acc[8]  += ex * c.x; acc[9]  += ex * c.y; acc[10] += ex * c.z; acc[11] += ex * c.w;
        acc[12] += ex * d.x; acc[13] += ex * d.y; acc[14] += ex * d.z; acc[15] += ex * d.w;
    }
    #pragma unroll
    for (int j = 0; j < 16; j++) acc[j] += acc2[j];
    denom += __shfl_xor_sync(~0u, denom, 16);
    #pragma unroll
    for (int j = 0; j < 16; j++) acc[j] += __shfl_xor_sync(~0u, acc[j], 16);
    if (half == 0) {
        float inv = 1.f / (denom + 1e-9f);
        float* op = g_o + ((size_t)g * NPG + dst) * DD + sub * 16;
        float4 v[4];
        #pragma unroll
        for (int j = 0; j < 16; j++) {
            float x = acc[j] * inv;
            ((float*)v)[j] = (x > 0.f) ? x : (__expf(x) - 1.f);
        }
        #pragma unroll
        for (int j = 0; j < 4; j++) ((float4*)op)[j] = v[j];
    }
}

// ---------------- 5: semantic score via bf16 tensor cores ----------------
#define SEMX_STRIDE 132
__global__ void k_sem(const float* __restrict__ semb,
                      const float* __restrict__ semq, const int* __restrict__ tgt) {
    __shared__ uint32_t sxb[32 * SEMX_STRIDE];
    __shared__ float sred[256];
    int g = blockIdx.y, b = g >> 1;
    int row0 = blockIdx.x * 32;
    int t = threadIdx.x;
    for (int i = t; i < 32 * 128; i += 256) {
        int r = i >> 7, c = i & 127;
        int node = tgt[g * TT + row0 + r];
        float2 xv = *(const float2*)(g_o + ((size_t)g * NPG + node) * DD + c * 2);
        sxb[r * SEMX_STRIDE + c] = bf2(xv.x, xv.y);
    }
    __syncthreads();
    int wid = t >> 5, lane = t & 31;
    int gid = lane >> 2, tid = lane & 3;
    int n0 = wid * 32;
    const uint32_t* Wb = (const uint32_t*)g_semWbt + (size_t)b * 32768;
    float c[2][4][4] = {};
    for (int ks = 0; ks < 16; ks++) {
        int abase = ks * 8 + tid;
        uint32_t a[2][4];
        #pragma unroll
        for (int mt = 0; mt < 2; mt++) {
            int r = mt * 16 + gid;
            a[mt][0] = sxb[r * SEMX_STRIDE + abase];
            a[mt][1] = sxb[(r + 8) * SEMX_STRIDE + abase];
            a[mt][2] = sxb[r * SEMX_STRIDE + abase + 4];
            a[mt][3] = sxb[(r + 8) * SEMX_STRIDE + abase + 4];
        }
        #pragma unroll
        for (int nt = 0; nt < 4; nt++) {
            int n = n0 + nt * 8 + gid;
            uint32_t b0 = Wb[n * 128 + ks * 8 + tid];
            uint32_t b1 = Wb[n * 128 + ks * 8 + tid + 4];
            #pragma unroll
            for (int mt = 0; mt < 2; mt++)
                mma_bf16(c[mt][nt][0], c[mt][nt][1], c[mt][nt][2], c[mt][nt][3],
                         a[mt][0], a[mt][1], a[mt][2], a[mt][3], b0, b1);
        }
    }
    float part = 0.f;
    #pragma unroll
    for (int nt = 0; nt < 4; nt++) {
        int col = n0 + nt * 8 + tid * 2;
        float2 bbv = *(const float2*)(semb + b * DD + col);
        float2 qqv = *(const float2*)(semq + b * DD + col);
        #pragma unroll
        for (int mt = 0; mt < 2; mt++) {
            part += tanh_fast(c[mt][nt][0] + bbv.x) * qqv.x;
            part += tanh_fast(c[mt][nt][1] + bbv.y) * qqv.y;
            part += tanh_fast(c[mt][nt][2] + bbv.x) * qqv.x;
            part += tanh_fast(c[mt][nt][3] + bbv.y) * qqv.y;
        }
    }
    sred[t] = part;
    __syncthreads();
    for (int s2 = 128; s2; s2 >>= 1) {
        if (t < s2) sred[t] += sred[t + s2];
        __syncthreads();
    }
    if (t == 0) atomicAdd(&g_wsum[g], sred[0]);
}

__global__ void k_beta() {
    if (threadIdx.x == 0 && blockIdx.x == 0) {
        for (int b = 0; b < 2; b++) {
            float w0 = g_wsum[b * 2 + 0] / (float)TT;
            float w1 = g_wsum[b * 2 + 1] / (float)TT;
            float mx = fmaxf(w0, w1);
            float e0 = __expf(w0 - mx), e1 = __expf(w1 - mx);
            float s = e0 + e1;
            g_beta[b * 2 + 0] = e0 / s;
            g_beta[b * 2 + 1] = e1 / s;
        }
    }
}

// ---------------- 6: beta-mix + fcout (32 rows/block, 256 thr) ----------------
#define OUT_PAD 34
__global__ void k_out(const float* __restrict__ foW, const float* __restrict__ fob,
                      const int* __restrict__ tgt, float* __restrict__ out) {
    int b = blockIdx.y;
    int row0 = blockIdx.x * 32;
    __shared__ float sx[256 * OUT_PAD];
    int t = threadIdx.x;
    float b0 = g_beta[b * 2], b1 = g_beta[b * 2 + 1];
    for (int i = t; i < 32 * 256; i += 256) {
        int r = i >> 8, k = i & 255;
        int row = row0 + r;
        int n0 = tgt[(b * 2 + 0) * TT + row];
        int n1 = tgt[(b * 2 + 1) * TT + row];
        sx[k * OUT_PAD + r] = b0 * g_o[((size_t)(b * 2 + 0) * NPG + n0) * DD + k]
                            + b1 * g_o[((size_t)(b * 2 + 1) * NPG + n1) * DD + k];
    }
    __syncthreads();
    int oq = t & 15, rg = t >> 4;
    const float* W = foW + (size_t)b * DD * OUTD;
    u64 acc0 = 0, acc1 = 0, acc2 = 0, acc3 = 0;
    #pragma unroll 4
    for (int k = 0; k < 256; k++) {
        float4 w = *(const float4*)(W + k * 64 + oq * 4);
        u64 xp = *(const u64*)&sx[k * OUT_PAD + rg * 2];
        u64 w0, w1, w2, w3;
        asm("mov.b64 %0, {%1, %1};" : "=l"(w0) : "f"(w.x));
        asm("mov.b64 %0, {%1, %1};" : "=l"(w1) : "f"(w.y));
        asm("mov.b64 %0, {%1, %1};" : "=l"(w2) : "f"(w.z));
        asm("mov.b64 %0, {%1, %1};" : "=l"(w3) : "f"(w.w));
        fma2(acc0, w0, xp); fma2(acc1, w1, xp);
        fma2(acc2, w2, xp); fma2(acc3, w3, xp);
    }
    float4 bb = *(const float4*)(fob + b * 64 + oq * 4);
    float2 a0 = unpack2(acc0), a1 = unpack2(acc1), a2 = unpack2(acc2), a3 = unpack2(acc3);
    int r0 = row0 + rg * 2;
    *(float4*)(out + ((size_t)b * TT + r0) * OUTD + oq * 4) =
        make_float4(a0.x + bb.x, a1.x + bb.y, a2.x + bb.z, a3.x + bb.w);
    *(float4*)(out + ((size_t)b * TT + r0 + 1) * OUTD + oq * 4) =
        make_float4(a0.y + bb.x, a1.y + bb.y, a2.y + bb.z, a3.y + bb.w);
}

// ---------------- launch ----------------
extern "C" void kernel_launch(void* const* d_in, const int* in_sizes, int n_in,
                              void* d_out, int out_size) {
    const float* features0 = (const float*)d_in[0];
    const float* features1 = (const float*)d_in[1];
    const float* fc_W      = (const float*)d_in[2];
    const float* fc_b      = (const float*)d_in[3];
    const float* gat_W     = (const float*)d_in[4];
    const float* attn_l    = (const float*)d_in[5];
    const float* attn_r    = (const float*)d_in[6];
    const float* sem_W     = (const float*)d_in[7];
    const float* sem_b     = (const float*)d_in[8];
    const float* sem_q     = (const float*)d_in[9];
    const float* fcout_W   = (const float*)d_in[10];
    const float* fcout_b   = (const float*)d_in[11];
    const int*   type_idx  = (const int*)d_in[12];
    const int*   node_idx  = (const int*)d_in[13];
    const int*   edge_src  = (const int*)d_in[14];
    const int*   edge_dst  = (const int*)d_in[15];
    const int*   tgt_idx   = (const int*)d_in[16];
    float* out = (float*)d_out;

    k_tw<<<768, 256>>>(fc_W, sem_W, gat_W);                     // 1
    k_zero<<<(NG * NPG + 255) / 256, 256>>>();                  // 2
    {
        dim3 grid((NPT + 31) / 32, 2);
        k_fc<<<grid, 256>>>(features0, features1, fc_b, type_idx);  // 3
    }
    {
        dim3 grid((NPG + 31) / 32, NG);
        k_gatz<<<grid, 256>>>(node_idx, attn_l, attn_r);        // 4 <- ncu capture slot
    }
    k_count<<<(NG * EG + 255) / 256, 256>>>(edge_dst);
    k_scan<<<NG, 1024>>>();
    k_scatter<<<(NG * EG + 255) / 256, 256>>>(edge_src, edge_dst);
    k_flag<<<(NG * TT + 255) / 256, 256>>>(tgt_idx);
    {
        dim3 grid((TT + 7) / 8, NG);
        k_agg<<<grid, 256>>>();
    }
    {
        dim3 grid(TT / 32, NG);
        k_sem<<<grid, 256>>>(sem_b, sem_q, tgt_idx);
    }
    k_beta<<<1, 32>>>();
    {
        dim3 grid(TT / 32, 2);
        k_out<<<grid, 256>>>(fcout_W, fcout_b, tgt_idx, out);
    }
}

// round 17
// speedup vs baseline: 1.0390x; 1.0390x over previous
#include <cuda_runtime.h>
#include <cuda_bf16.h>
#include <cstdint>
#include <cstddef>

// ---------------- problem constants ----------------
#define NTOT   100000
#define NPT    50000
#define NPG    50000
#define EG     500000
#define NG     4
#define NH     4
#define HD     64
#define HID    64
#define DD     256
#define OUTD   64
#define TT     20000

typedef unsigned long long u64;

// ---------------- device scratch (static, no allocs) ----------------
__device__ float g_transformed[(size_t)NTOT * HID];
__device__ __nv_bfloat16 g_semWbt[2 * 256 * 256];      // sem_W bf16 transposed [b][n][k]
__device__ uint32_t g_gatWhi[4 * 256 * 32];            // gat_W bf16 hi [g][n][kpair]
__device__ uint32_t g_gatWlo[4 * 256 * 32];            // gat_W bf16 lo residual
__device__ uint32_t g_fcWhi[2 * 64 * 128];             // fc_W bf16 hi [ty][n][kpair]
__device__ uint32_t g_fcWlo[2 * 64 * 128];             // fc_W bf16 lo residual
__device__ float g_z[(size_t)NG * NPG * DD];
__device__ float g_el[NG * NPG * NH];
__device__ float g_er[NG * NPG * NH];
__device__ int   g_cnt[NG * NPG];
__device__ int   g_cur[NG * NPG];
__device__ int   g_offs[NG * (NPG + 1)];
__device__ int   g_csr[NG * EG];
__device__ int   g_flag[NG * NPG];
__device__ int   g_list[NG * TT];
__device__ int   g_wcnt[NG];
__device__ float g_o[(size_t)NG * NPG * DD];
__device__ float g_wsum[NG];
__device__ float g_beta[NG];

__device__ __forceinline__ float lrelu(float x) { return fmaxf(x, 0.2f * x); }
__device__ __forceinline__ float tanh_fast(float x) {
    float y; asm("tanh.approx.f32 %0, %1;" : "=f"(y) : "f"(x)); return y;
}
__device__ __forceinline__ void fma2(u64& acc, u64 a, u64 b) {
    asm("fma.rn.f32x2 %0, %1, %2, %0;" : "+l"(acc) : "l"(a), "l"(b));
}
__device__ __forceinline__ float2 unpack2(u64 v) {
    float2 r; asm("mov.b64 {%0, %1}, %2;" : "=f"(r.x), "=f"(r.y) : "l"(v)); return r;
}
// pack (lo,hi) floats into bf16x2 (lo = element 0)
__device__ __forceinline__ uint32_t bf2(float lo, float hi) {
    uint32_t r; asm("cvt.rn.bf16x2.f32 %0, %1, %2;" : "=r"(r) : "f"(hi), "f"(lo)); return r;
}
__device__ __forceinline__ void mma_bf16(float& c0, float& c1, float& c2, float& c3,
                                         uint32_t a0, uint32_t a1, uint32_t a2, uint32_t a3,
                                         uint32_t b0, uint32_t b1) {
    asm("mma.sync.aligned.m16n8k16.row.col.f32.bf16.bf16.f32 "
        "{%0,%1,%2,%3},{%4,%5,%6,%7},{%8,%9},{%0,%1,%2,%3};"
        : "+f"(c0), "+f"(c1), "+f"(c2), "+f"(c3)
        : "r"(a0), "r"(a1), "r"(a2), "r"(a3), "r"(b0), "r"(b1));
}

// ---------------- weight prep ----------------
__global__ void k_tw(const float* __restrict__ fcW, const float* __restrict__ semW,
                     const float* __restrict__ gatW) {
    int i = blockIdx.x * blockDim.x + threadIdx.x;
    if (i < 2 * 256 * 256) {                   // semWbt [b][n][k] <- semW [b][k][n]
        int b = i >> 16, rem = i & 65535, n = rem >> 8, k = rem & 255;
        g_semWbt[i] = __float2bfloat16(semW[b * 65536 + k * 256 + n]);
    }
    int j2 = i - 2 * 256 * 256;
    if (j2 >= 0 && j2 < 4 * 256 * 32) {        // gat hi/lo [g][n][kpair]
        int g = j2 >> 13, rem = j2 & 8191, n = rem >> 5, kp = rem & 31;
        const float* Wg = gatW + (size_t)g * 64 * 256;
        float w0 = Wg[(2 * kp) * 256 + n];
        float w1 = Wg[(2 * kp + 1) * 256 + n];
        uint32_t hp = bf2(w0, w1);
        g_gatWhi[j2] = hp;
        float h0 = __uint_as_float(hp << 16);
        float h1 = __uint_as_float(hp & 0xffff0000u);
        g_gatWlo[j2] = bf2(w0 - h0, w1 - h1);
    }
    int j3 = i - 2 * 256 * 256 - 4 * 256 * 32;
    if (j3 >= 0 && j3 < 2 * 64 * 128) {        // fc hi/lo [ty][n][kpair], fcW is [ty][o][k]
        int ty = j3 >> 13, rem = j3 & 8191, n = rem >> 7, kp = rem & 127;
        const float* Wt = fcW + ty * 16384 + n * 256;
        float w0 = Wt[2 * kp];
        float w1 = Wt[2 * kp + 1];
        uint32_t hp = bf2(w0, w1);
        g_fcWhi[j3] = hp;
        float h0 = __uint_as_float(hp << 16);
        float h1 = __uint_as_float(hp & 0xffff0000u);
        g_fcWlo[j3] = bf2(w0 - h0, w1 - h1);
    }
}

// ---------------- zero per-call scratch ----------------
__global__ void k_zero() {
    int i = blockIdx.x * blockDim.x + threadIdx.x;
    if (i < NG * NPG) { g_cnt[i] = 0; g_cur[i] = 0; g_flag[i] = 0; }
    if (i < NG) { g_wsum[i] = 0.f; g_wcnt[i] = 0; }
}

// ---------------- 1: type FC via split-bf16 MMA  [R15 verbatim] ----------------
#define FC_S 132
__global__ void k_fc(const float* __restrict__ f0, const float* __restrict__ f1,
                     const float* __restrict__ fcb, const int* __restrict__ type_idx) {
    __shared__ uint32_t ahi[32 * FC_S], alo[32 * FC_S];
    int ty = blockIdx.y;
    int row0 = blockIdx.x * 32;
    int t = threadIdx.x;
    const float* f = (ty == 0 ? f0 : f1);
    for (int i = t; i < 32 * 128; i += 256) {
        int r = i >> 7, c = i & 127;
        int rr = row0 + r; rr = rr < NPT ? rr : NPT - 1;
        float2 xv = *(const float2*)(f + (size_t)rr * 256 + c * 2);
        uint32_t hp = bf2(xv.x, xv.y);
        float h0 = __uint_as_float(hp << 16);
        float h1 = __uint_as_float(hp & 0xffff0000u);
        ahi[r * FC_S + c] = hp;
        alo[r * FC_S + c] = bf2(xv.x - h0, xv.y - h1);
    }
    __syncthreads();
    int wid = t >> 5, lane = t & 31;
    int gid = lane >> 2, tid = lane & 3;
    int mt = wid >> 2, cq = wid & 3;
    const uint32_t* Whi = g_fcWhi + ty * 8192;   // [n=64][kp=128]
    const uint32_t* Wlo = g_fcWlo + ty * 8192;
    float c[2][4] = {};                          // [ntile][reg]
    #pragma unroll
    for (int ks = 0; ks < 16; ks++) {
        int ab = ks * 8 + tid;
        int r = mt * 16 + gid;
        uint32_t a0 = ahi[r * FC_S + ab];
        uint32_t a1 = ahi[(r + 8) * FC_S + ab];
        uint32_t a2 = ahi[r * FC_S + ab + 4];
        uint32_t a3 = ahi[(r + 8) * FC_S + ab + 4];
        uint32_t v0 = alo[r * FC_S + ab];
        uint32_t v1 = alo[(r + 8) * FC_S + ab];
        uint32_t v2 = alo[r * FC_S + ab + 4];
        uint32_t v3 = alo[(r + 8) * FC_S + ab + 4];
        #pragma unroll
        for (int nt = 0; nt < 2; nt++) {
            int n = cq * 16 + nt * 8 + gid;
            uint32_t bh0 = Whi[n * 128 + ks * 8 + tid];
            uint32_t bh1 = Whi[n * 128 + ks * 8 + tid + 4];
            uint32_t bl0 = Wlo[n * 128 + ks * 8 + tid];
            uint32_t bl1 = Wlo[n * 128 + ks * 8 + tid + 4];
            mma_bf16(c[nt][0], c[nt][1], c[nt][2], c[nt][3], a0, a1, a2, a3, bh0, bh1);
            mma_bf16(c[nt][0], c[nt][1], c[nt][2], c[nt][3], a0, a1, a2, a3, bl0, bl1);
            mma_bf16(c[nt][0], c[nt][1], c[nt][2], c[nt][3], v0, v1, v2, v3, bh0, bh1);
        }
    }
    #pragma unroll
    for (int nt = 0; nt < 2; nt++) {
        int col = cq * 16 + nt * 8 + tid * 2;
        float2 bbv = *(const float2*)(fcb + ty * 64 + col);
        int r0 = row0 + mt * 16 + gid;
        if (r0 < NPT) {
            int d = type_idx[ty * NPT + r0];
            *(float2*)(g_transformed + (size_t)d * 64 + col) =
                make_float2(c[nt][0] + bbv.x, c[nt][1] + bbv.y);
        }
        if (r0 + 8 < NPT) {
            int d = type_idx[ty * NPT + r0 + 8];
            *(float2*)(g_transformed + (size_t)d * 64 + col) =
                make_float2(c[nt][2] + bbv.x, c[nt][3] + bbv.y);
        }
    }
}

// ---------------- 2: gather + z = h @ gat_W via split-bf16 MMA, fused el/er  [R15 verbatim] ----------------
#define GA_S 36
__global__ void k_gatz(const int* __restrict__ node_idx,
                       const float* __restrict__ al, const float* __restrict__ ar) {
    __shared__ uint32_t ahi[32 * GA_S], alo[32 * GA_S];
    __shared__ float sel[32][NH], ser[32][NH];
    int g = blockIdx.y;
    int row0 = blockIdx.x * 32;
    int t = threadIdx.x;
    if (t < 128) { sel[t >> 2][t & 3] = 0.f; ser[t >> 2][t & 3] = 0.f; }
    for (int i = t; i < 32 * 32; i += 256) {
        int r = i >> 5, c = i & 31;
        int rr = row0 + r; rr = rr < NPG ? rr : NPG - 1;
        int node = node_idx[g * NPG + rr];
        float2 xv = *(const float2*)(g_transformed + (size_t)node * 64 + c * 2);
        uint32_t hp = bf2(xv.x, xv.y);
        float h0 = __uint_as_float(hp << 16);
        float h1 = __uint_as_float(hp & 0xffff0000u);
        ahi[r * GA_S + c] = hp;
        alo[r * GA_S + c] = bf2(xv.x - h0, xv.y - h1);
    }
    __syncthreads();
    int wid = t >> 5, lane = t & 31;
    int gid = lane >> 2, tid = lane & 3;
    int n0 = wid * 32;
    const uint32_t* Whi = g_gatWhi + (size_t)g * 8192;
    const uint32_t* Wlo = g_gatWlo + (size_t)g * 8192;
    float c[2][4][4] = {};
    #pragma unroll
    for (int ks = 0; ks < 4; ks++) {
        int ab = ks * 8 + tid;
        uint32_t ah[2][4], av[2][4];
        #pragma unroll
        for (int mt = 0; mt < 2; mt++) {
            int r = mt * 16 + gid;
            ah[mt][0] = ahi[r * GA_S + ab];           av[mt][0] = alo[r * GA_S + ab];
            ah[mt][1] = ahi[(r + 8) * GA_S + ab];     av[mt][1] = alo[(r + 8) * GA_S + ab];
            ah[mt][2] = ahi[r * GA_S + ab + 4];       av[mt][2] = alo[r * GA_S + ab + 4];
            ah[mt][3] = ahi[(r + 8) * GA_S + ab + 4]; av[mt][3] = alo[(r + 8) * GA_S + ab + 4];
        }
        #pragma unroll
        for (int nt = 0; nt < 4; nt++) {
            int n = n0 + nt * 8 + gid;
            uint32_t bh0 = Whi[n * 32 + ks * 8 + tid];
            uint32_t bh1 = Whi[n * 32 + ks * 8 + tid + 4];
            uint32_t bl0 = Wlo[n * 32 + ks * 8 + tid];
            uint32_t bl1 = Wlo[n * 32 + ks * 8 + tid + 4];
            #pragma unroll
            for (int mt = 0; mt < 2; mt++) {
                mma_bf16(c[mt][nt][0], c[mt][nt][1], c[mt][nt][2], c[mt][nt][3],
                         ah[mt][0], ah[mt][1], ah[mt][2], ah[mt][3], bh0, bh1);
                mma_bf16(c[mt][nt][0], c[mt][nt][1], c[mt][nt][2], c[mt][nt][3],
                         ah[mt][0], ah[mt][1], ah[mt][2], ah[mt][3], bl0, bl1);
                mma_bf16(c[mt][nt][0], c[mt][nt][1], c[mt][nt][2], c[mt][nt][3],
                         av[mt][0], av[mt][1], av[mt][2], av[mt][3], bh0, bh1);
            }
        }
    }
    float pl[2][2] = {}, pr[2][2] = {};
    #pragma unroll
    for (int mt = 0; mt < 2; mt++) {
        #pragma unroll
        for (int nt = 0; nt < 4; nt++) {
            int col = n0 + nt * 8 + tid * 2;
            float2 av2 = *(const float2*)(al + g * DD + col);
            float2 rv2 = *(const float2*)(ar + g * DD + col);
            pl[mt][0] += c[mt][nt][0] * av2.x + c[mt][nt][1] * av2.y;
            pl[mt][1] += c[mt][nt][2] * av2.x + c[mt][nt][3] * av2.y;
            pr[mt][0] += c[mt][nt][0] * rv2.x + c[mt][nt][1] * rv2.y;
            pr[mt][1] += c[mt][nt][2] * rv2.x + c[mt][nt][3] * rv2.y;
            int r0 = row0 + mt * 16 + gid;
            if (r0 < NPG)
                *(float2*)(g_z + ((size_t)g * NPG + r0) * DD + col) =
                    make_float2(c[mt][nt][0], c[mt][nt][1]);
            if (r0 + 8 < NPG)
                *(float2*)(g_z + ((size_t)g * NPG + r0 + 8) * DD + col) =
                    make_float2(c[mt][nt][2], c[mt][nt][3]);
        }
    }
    #pragma unroll
    for (int off = 1; off < 4; off <<= 1) {
        #pragma unroll
        for (int mt = 0; mt < 2; mt++) {
            #pragma unroll
            for (int rp = 0; rp < 2; rp++) {
                pl[mt][rp] += __shfl_xor_sync(~0u, pl[mt][rp], off);
                pr[mt][rp] += __shfl_xor_sync(~0u, pr[mt][rp], off);
            }
        }
    }
    if (tid == 0) {
        int h = wid >> 1;
        #pragma unroll
        for (int mt = 0; mt < 2; mt++) {
            #pragma unroll
            for (int rp = 0; rp < 2; rp++) {
                int r = mt * 16 + gid + rp * 8;
                atomicAdd(&sel[r][h], pl[mt][rp]);
                atomicAdd(&ser[r][h], pr[mt][rp]);
            }
        }
    }
    __syncthreads();
    if (t < 128) {
        int r = t >> 2, h = t & 3;
        int row = row0 + r;
        if (row < NPG) {
            g_el[((size_t)g * NPG + row) * NH + h] = sel[r][h];
            g_er[((size_t)g * NPG + row) * NH + h] = ser[r][h];
        }
    }
}

// ---------------- 3: CSR build ----------------
__global__ void k_count(const int* __restrict__ edst) {
    int i = blockIdx.x * blockDim.x + threadIdx.x;
    if (i < NG * EG) { int g = i / EG; atomicAdd(&g_cnt[g * NPG + edst[i]], 1); }
}

__global__ void k_scan() {
    int g = blockIdx.x;
    __shared__ int ssum[1024];
    int t = threadIdx.x;
    const int per = (NPG + 1023) / 1024;
    int beg = t * per, end = min(beg + per, NPG);
    int s = 0;
    for (int i = beg; i < end; i++) s += g_cnt[g * NPG + i];
    ssum[t] = s;
    __syncthreads();
    for (int off = 1; off < 1024; off <<= 1) {
        int v = (t >= off) ? ssum[t - off] : 0;
        __syncthreads();
        ssum[t] += v;
        __syncthreads();
    }
    int run = (t == 0) ? 0 : ssum[t - 1];
    for (int i = beg; i < end; i++) { g_offs[g * (NPG + 1) + i] = run; run += g_cnt[g * NPG + i]; }
    if (t == 1023) g_offs[g * (NPG + 1) + NPG] = run;
}

__global__ void k_scatter(const int* __restrict__ esrc, const int* __restrict__ edst) {
    int i = blockIdx.x * blockDim.x + threadIdx.x;
    if (i < NG * EG) {
        int g = i / EG;
        int d = edst[i];
        int pos = g_offs[g * (NPG + 1) + d] + atomicAdd(&g_cur[g * NPG + d], 1);
        g_csr[g * EG + pos] = esrc[i];
    }
}

__global__ void k_flag(const int* __restrict__ tgt) {
    int i = blockIdx.x * blockDim.x + threadIdx.x;
    if (i < NG * TT) {
        int g = i / TT;
        int d = tgt[i];
        if (atomicExch(&g_flag[g * NPG + d], 1) == 0) {
            int p = atomicAdd(&g_wcnt[g], 1);
            g_list[g * TT + p] = d;
        }
    }
}

// ---------------- 4: edge softmax + aggregation, 2 warps per dst (128 cols each) ----------------
__global__ void k_agg() {
    int g = blockIdx.y;
    int wid = threadIdx.x >> 5;
    int widx = blockIdx.x * 4 + (wid >> 1);
    if (widx >= g_wcnt[g]) return;
    int cw   = wid & 1;               // column half: cols cw*128 .. cw*128+127
    int lane = threadIdx.x & 31;
    int half = lane >> 4;             // edge parity
    int sub  = lane & 15;
    int colb = cw * 128 + sub * 8;    // 8 cols per lane, within one head
    int h    = colb >> 6;
    int dst  = g_list[g * TT + widx];
    int beg = g_offs[g * (NPG + 1) + dst];
    int end = g_offs[g * (NPG + 1) + dst + 1];
    const int*   csr = g_csr + g * EG;
    const float* elg = g_el + (size_t)g * NPG * NH;
    const float* zg  = g_z + (size_t)g * NPG * DD;
    float erh = g_er[(g * NPG + dst) * NH + h];
    float acc[8] = {};
    float denom = 0.f;
    for (int i = beg + half; i < end; i += 2) {
        int src = csr[i];
        float e  = lrelu(elg[src * NH + h] + erh);
        float ex = __expf(e);
        denom += ex;
        const float4* zp = (const float4*)(zg + (size_t)src * DD + colb);
        float4 a = zp[0], b = zp[1];
        acc[0] += ex * a.x; acc[1] += ex * a.y; acc[2] += ex * a.z; acc[3] += ex * a.w;
        acc[4] += ex * b.x; acc[5] += ex * b.y; acc[6] += ex * b.z; acc[7] += ex * b.w;
    }
    denom += __shfl_xor_sync(~0u, denom, 16);
    #pragma unroll
    for (int j = 0; j < 8; j++) acc[j] += __shfl_xor_sync(~0u, acc[j], 16);
    if (half == 0) {
        float inv = 1.f / (denom + 1e-9f);
        float* op = g_o + ((size_t)g * NPG + dst) * DD + colb;
        float4 v[2];
        #pragma unroll
        for (int j = 0; j < 8; j++) {
            float x = acc[j] * inv;
            ((float*)v)[j] = (x > 0.f) ? x : (__expf(x) - 1.f);
        }
        ((float4*)op)[0] = v[0];
        ((float4*)op)[1] = v[1];
    }
}

// ---------------- 5: semantic score via bf16 tensor cores  [R15 verbatim] ----------------
#define SEMX_STRIDE 132
__global__ void k_sem(const float* __restrict__ semb,
                      const float* __restrict__ semq, const int* __restrict__ tgt) {
    __shared__ uint32_t sxb[32 * SEMX_STRIDE];
    __shared__ float sred[256];
    int g = blockIdx.y, b = g >> 1;
    int row0 = blockIdx.x * 32;
    int t = threadIdx.x;
    for (int i = t; i < 32 * 128; i += 256) {
        int r = i >> 7, c = i & 127;
        int node = tgt[g * TT + row0 + r];
        float2 xv = *(const float2*)(g_o + ((size_t)g * NPG + node) * DD + c * 2);
        sxb[r * SEMX_STRIDE + c] = bf2(xv.x, xv.y);
    }
    __syncthreads();
    int wid = t >> 5, lane = t & 31;
    int gid = lane >> 2, tid = lane & 3;
    int n0 = wid * 32;
    const uint32_t* Wb = (const uint32_t*)g_semWbt + (size_t)b * 32768;
    float c[2][4][4] = {};
    for (int ks = 0; ks < 16; ks++) {
        int abase = ks * 8 + tid;
        uint32_t a[2][4];
        #pragma unroll
        for (int mt = 0; mt < 2; mt++) {
            int r = mt * 16 + gid;
            a[mt][0] = sxb[r * SEMX_STRIDE + abase];
            a[mt][1] = sxb[(r + 8) * SEMX_STRIDE + abase];
            a[mt][2] = sxb[r * SEMX_STRIDE + abase + 4];
            a[mt][3] = sxb[(r + 8) * SEMX_STRIDE + abase + 4];
        }
        #pragma unroll
        for (int nt = 0; nt < 4; nt++) {
            int n = n0 + nt * 8 + gid;
            uint32_t b0 = Wb[n * 128 + ks * 8 + tid];
            uint32_t b1 = Wb[n * 128 + ks * 8 + tid + 4];
            #pragma unroll
            for (int mt = 0; mt < 2; mt++)
                mma_bf16(c[mt][nt][0], c[mt][nt][1], c[mt][nt][2], c[mt][nt][3],
                         a[mt][0], a[mt][1], a[mt][2], a[mt][3], b0, b1);
        }
    }
    float part = 0.f;
    #pragma unroll
    for (int nt = 0; nt < 4; nt++) {
        int col = n0 + nt * 8 + tid * 2;
        float2 bbv = *(const float2*)(semb + b * DD + col);
        float2 qqv = *(const float2*)(semq + b * DD + col);
        #pragma unroll
        for (int mt = 0; mt < 2; mt++) {
            part += tanh_fast(c[mt][nt][0] + bbv.x) * qqv.x;
            part += tanh_fast(c[mt][nt][1] + bbv.y) * qqv.y;
            part += tanh_fast(c[mt][nt][2] + bbv.x) * qqv.x;
            part += tanh_fast(c[mt][nt][3] + bbv.y) * qqv.y;
        }
    }
    sred[t] = part;
    __syncthreads();
    for (int s2 = 128; s2; s2 >>= 1) {
        if (t < s2) sred[t] += sred[t + s2];
        __syncthreads();
    }
    if (t == 0) atomicAdd(&g_wsum[g], sred[0]);
}

__global__ void k_beta() {
    if (threadIdx.x == 0 && blockIdx.x == 0) {
        for (int b = 0; b < 2; b++) {
            float w0 = g_wsum[b * 2 + 0] / (float)TT;
            float w1 = g_wsum[b * 2 + 1] / (float)TT;
            float mx = fmaxf(w0, w1);
            float e0 = __expf(w0 - mx), e1 = __expf(w1 - mx);
            float s = e0 + e1;
            g_beta[b * 2 + 0] = e0 / s;
            g_beta[b * 2 + 1] = e1 / s;
        }
    }
}

// ---------------- 6: beta-mix + fcout (32 rows/block, 256 thr)  [R15 verbatim] ----------------
#define OUT_PAD 34
__global__ void k_out(const float* __restrict__ foW, const float* __restrict__ fob,
                      const int* __restrict__ tgt, float* __restrict__ out) {
    int b = blockIdx.y;
    int row0 = blockIdx.x * 32;
    __shared__ float sx[256 * OUT_PAD];
    int t = threadIdx.x;
    float b0 = g_beta[b * 2], b1 = g_beta[b * 2 + 1];
    for (int i = t; i < 32 * 256; i += 256) {
        int r = i >> 8, k = i & 255;
        int row = row0 + r;
        int n0 = tgt[(b * 2 + 0) * TT + row];
        int n1 = tgt[(b * 2 + 1) * TT + row];
        sx[k * OUT_PAD + r] = b0 * g_o[((size_t)(b * 2 + 0) * NPG + n0) * DD + k]
                            + b1 * g_o[((size_t)(b * 2 + 1) * NPG + n1) * DD + k];
    }
    __syncthreads();
    int oq = t & 15, rg = t >> 4;
    const float* W = foW + (size_t)b * DD * OUTD;
    u64 acc0 = 0, acc1 = 0, acc2 = 0, acc3 = 0;
    #pragma unroll 4
    for (int k = 0; k < 256; k++) {
        float4 w = *(const float4*)(W + k * 64 + oq * 4);
        u64 xp = *(const u64*)&sx[k * OUT_PAD + rg * 2];
        u64 w0, w1, w2, w3;
        asm("mov.b64 %0, {%1, %1};" : "=l"(w0) : "f"(w.x));
        asm("mov.b64 %0, {%1, %1};" : "=l"(w1) : "f"(w.y));
        asm("mov.b64 %0, {%1, %1};" : "=l"(w2) : "f"(w.z));
        asm("mov.b64 %0, {%1, %1};" : "=l"(w3) : "f"(w.w));
        fma2(acc0, w0, xp); fma2(acc1, w1, xp);
        fma2(acc2, w2, xp); fma2(acc3, w3, xp);
    }
    float4 bb = *(const float4*)(fob + b * 64 + oq * 4);
    float2 a0 = unpack2(acc0), a1 = unpack2(acc1), a2 = unpack2(acc2), a3 = unpack2(acc3);
    int r0 = row0 + rg * 2;
    *(float4*)(out + ((size_t)b * TT + r0) * OUTD + oq * 4) =
        make_float4(a0.x + bb.x, a1.x + bb.y, a2.x + bb.z, a3.x + bb.w);
    *(float4*)(out + ((size_t)b * TT + r0 + 1) * OUTD + oq * 4) =
        make_float4(a0.y + bb.x, a1.y + bb.y, a2.y + bb.z, a3.y + bb.w);
}

// ---------------- launch ----------------
extern "C" void kernel_launch(void* const* d_in, const int* in_sizes, int n_in,
                              void* d_out, int out_size) {
    const float* features0 = (const float*)d_in[0];
    const float* features1 = (const float*)d_in[1];
    const float* fc_W      = (const float*)d_in[2];
    const float* fc_b      = (const float*)d_in[3];
    const float* gat_W     = (const float*)d_in[4];
    const float* attn_l    = (const float*)d_in[5];
    const float* attn_r    = (const float*)d_in[6];
    const float* sem_W     = (const float*)d_in[7];
    const float* sem_b     = (const float*)d_in[8];
    const float* sem_q     = (const float*)d_in[9];
    const float* fcout_W   = (const float*)d_in[10];
    const float* fcout_b   = (const float*)d_in[11];
    const int*   type_idx  = (const int*)d_in[12];
    const int*   node_idx  = (const int*)d_in[13];
    const int*   edge_src  = (const int*)d_in[14];
    const int*   edge_dst  = (const int*)d_in[15];
    const int*   tgt_idx   = (const int*)d_in[16];
    float* out = (float*)d_out;

    k_tw<<<768, 256>>>(fc_W, sem_W, gat_W);                     // 1
    k_zero<<<(NG * NPG + 255) / 256, 256>>>();                  // 2
    {
        dim3 grid((NPT + 31) / 32, 2);
        k_fc<<<grid, 256>>>(features0, features1, fc_b, type_idx);  // 3
    }
    {
        dim3 grid((NPG + 31) / 32, NG);
        k_gatz<<<grid, 256>>>(node_idx, attn_l, attn_r);        // 4 <- ncu capture slot
    }
    k_count<<<(NG * EG + 255) / 256, 256>>>(edge_dst);
    k_scan<<<NG, 1024>>>();
    k_scatter<<<(NG * EG + 255) / 256, 256>>>(edge_src, edge_dst);
    k_flag<<<(NG * TT + 255) / 256, 256>>>(tgt_idx);
    {
        dim3 grid((TT + 3) / 4, NG);   // 4 dsts per block, 2 warps per dst
        k_agg<<<grid, 256>>>();
    }
    {
        dim3 grid(TT / 32, NG);
        k_sem<<<grid, 256>>>(sem_b, sem_q, tgt_idx);
    }
    k_beta<<<1, 32>>>();
    {
        dim3 grid(TT / 32, 2);
        k_out<<<grid, 256>>>(fcout_W, fcout_b, tgt_idx, out);
    }
}